// round 2
// baseline (speedup 1.0000x reference)
#include <cuda_runtime.h>
#include <cuda_bf16.h>
#include <math.h>

// ---------------- problem constants ----------------
#define S_LEN   2048
#define HID     3584
#define NH      16
#define NKV     8
#define HD      256
#define GROUPS  2
#define WINDOW  1024

// scratch (device globals; no allocation allowed)
__device__ float g_q [S_LEN * NH  * HD];   // [s, h, d]   32 MB
__device__ float g_k [S_LEN * NKV * HD];   // [s, kh, d]  16 MB
__device__ float g_v [S_LEN * NKV * HD];   // [s, kh, d]  16 MB
__device__ float g_ao[S_LEN * NH  * HD];   // attention out, 32 MB

// =====================================================================
// SGEMM:  C[M,N] = A[M,K] * B[N,K]^T   (both row-major, K contiguous)
// 128x128 tile, BK=8, 256 threads, 8x8 per-thread microtile.
// M, N, K all divisible by 128 / 8 for every call in this problem.
// =====================================================================
__global__ __launch_bounds__(256) void sgemm_tn(
    const float* __restrict__ A, const float* __restrict__ B,
    float* __restrict__ C, int M, int N, int K)
{
    __shared__ float As[8][128];
    __shared__ float Bs[8][128];

    const int tid  = threadIdx.x;
    const int row0 = blockIdx.y * 128;
    const int col0 = blockIdx.x * 128;

    const int lrow = tid >> 1;         // 0..127
    const int lcol = (tid & 1) * 4;    // 0 or 4

    const float* Aptr = A + (size_t)(row0 + lrow) * K + lcol;
    const float* Bptr = B + (size_t)(col0 + lrow) * K + lcol;

    const int tr = tid >> 4;   // 0..15 -> rows tr*8..tr*8+7
    const int tc = tid & 15;   // 0..15 -> cols tc*8..tc*8+7

    float acc[8][8];
    #pragma unroll
    for (int i = 0; i < 8; i++)
        #pragma unroll
        for (int j = 0; j < 8; j++) acc[i][j] = 0.f;

    const int nk = K >> 3;
    float4 a4 = *(const float4*)Aptr;
    float4 b4 = *(const float4*)Bptr;

    for (int kt = 0; kt < nk; ++kt) {
        As[lcol + 0][lrow] = a4.x; As[lcol + 1][lrow] = a4.y;
        As[lcol + 2][lrow] = a4.z; As[lcol + 3][lrow] = a4.w;
        Bs[lcol + 0][lrow] = b4.x; Bs[lcol + 1][lrow] = b4.y;
        Bs[lcol + 2][lrow] = b4.z; Bs[lcol + 3][lrow] = b4.w;
        __syncthreads();

        if (kt + 1 < nk) {
            a4 = *(const float4*)(Aptr + (size_t)(kt + 1) * 8);
            b4 = *(const float4*)(Bptr + (size_t)(kt + 1) * 8);
        }

        #pragma unroll
        for (int k = 0; k < 8; ++k) {
            float ra[8], rb[8];
            *(float4*)&ra[0] = *(const float4*)&As[k][tr * 8];
            *(float4*)&ra[4] = *(const float4*)&As[k][tr * 8 + 4];
            *(float4*)&rb[0] = *(const float4*)&Bs[k][tc * 8];
            *(float4*)&rb[4] = *(const float4*)&Bs[k][tc * 8 + 4];
            #pragma unroll
            for (int i = 0; i < 8; i++)
                #pragma unroll
                for (int j = 0; j < 8; j++)
                    acc[i][j] += ra[i] * rb[j];
        }
        __syncthreads();
    }

    #pragma unroll
    for (int i = 0; i < 8; i++) {
        float* cp = C + (size_t)(row0 + tr * 8 + i) * N + col0 + tc * 8;
        float4 c0 = make_float4(acc[i][0], acc[i][1], acc[i][2], acc[i][3]);
        float4 c1 = make_float4(acc[i][4], acc[i][5], acc[i][6], acc[i][7]);
        *(float4*)cp       = c0;
        *(float4*)(cp + 4) = c1;
    }
}

// =====================================================================
// RoPE in-place: x layout [s, nheads, 256].
// cos/sin: [s, 256] with cos[s][d] == cos[s][d+128] by construction.
// =====================================================================
__global__ void rope_kernel(float* __restrict__ x,
                            const float* __restrict__ cosb,
                            const float* __restrict__ sinb,
                            int nheads)
{
    int idx = blockIdx.x * blockDim.x + threadIdx.x;
    int total = S_LEN * nheads * 128;
    if (idx >= total) return;
    int d = idx & 127;
    int t = idx >> 7;
    int h = t % nheads;
    int s = t / nheads;
    float c  = cosb[s * HD + d];
    float sn = sinb[s * HD + d];
    float* p = x + ((size_t)s * nheads + h) * HD;
    float x1 = p[d], x2 = p[d + 128];
    p[d]       = x1 * c - x2 * sn;
    p[d + 128] = x2 * c + x1 * sn;
}

// =====================================================================
// Flash-style sliding-window attention with softcap.
// grid = (S/64, NH), 256 threads.
// Each block: 64 queries of one head. Key tiles of 32, online softmax.
// Thread layout: ty = tid/16 (0..15), tx = tid%16.
//   rows owned:   i = ty + 16r,  r in 0..3
//   score cols:   j = tx + 16c,  c in 0..1
//   O cols owned: d = tx + 16k,  k in 0..15
// =====================================================================
#define ABM   64
#define ABN   32
#define KPAD  260   // 260*4 bytes per row, 16B-aligned, conflict-free
#define ATTN_SMEM ((ABM*HD + 2*ABN*KPAD + ABM*ABN) * sizeof(float))

__global__ __launch_bounds__(256) void attn_kernel(
    const float* __restrict__ Q, const float* __restrict__ Kb,
    const float* __restrict__ Vb, float* __restrict__ O)
{
    extern __shared__ float sm[];
    float* Qs = sm;                      // [64][256]
    float* Ks = Qs + ABM * HD;           // [32][260]
    float* Vs = Ks + ABN * KPAD;         // [32][260]
    float* Ps = Vs + ABN * KPAD;         // [64][32]

    const int tid = threadIdx.x;
    const int tx = tid & 15, ty = tid >> 4;
    const int q0 = blockIdx.x * ABM;
    const int h  = blockIdx.y;
    const int kvh = h / GROUPS;

    // ---- load Q tile ----
    #pragma unroll
    for (int t = 0; t < 16; ++t) {
        int f4  = tid + 256 * t;            // 4096 float4 total
        int row = f4 >> 6;                  // 64 float4 per row
        int c4  = (f4 & 63) << 2;
        float4 v = *(const float4*)(Q + ((size_t)(q0 + row) * NH + h) * HD + c4);
        *(float4*)(Qs + row * HD + c4) = v;
    }

    float o[4][16];
    float mrow[4], lrow[4];
    #pragma unroll
    for (int r = 0; r < 4; r++) {
        mrow[r] = -1e30f; lrow[r] = 0.f;
        #pragma unroll
        for (int k = 0; k < 16; k++) o[r][k] = 0.f;
    }

    int jlo = q0 - (WINDOW - 1); if (jlo < 0) jlo = 0;
    const int t0   = (jlo >> 5) << 5;
    const int tend = q0 + ABM;

    __syncthreads();  // Qs visible

    for (int kb = t0; kb < tend; kb += ABN) {
        // ---- load K,V tile ----
        #pragma unroll
        for (int t = 0; t < 8; ++t) {
            int f4  = tid + 256 * t;        // 2048 float4
            int row = f4 >> 6;
            int c4  = (f4 & 63) << 2;
            size_t gb = ((size_t)(kb + row) * NKV + kvh) * HD + c4;
            *(float4*)(Ks + row * KPAD + c4) = *(const float4*)(Kb + gb);
            *(float4*)(Vs + row * KPAD + c4) = *(const float4*)(Vb + gb);
        }
        __syncthreads();

        // ---- scores: S = Q K^T ----
        float sc[4][2];
        #pragma unroll
        for (int r = 0; r < 4; r++) { sc[r][0] = 0.f; sc[r][1] = 0.f; }

        #pragma unroll 4
        for (int dd = 0; dd < HD; dd += 4) {
            float4 k0 = *(const float4*)(Ks + tx * KPAD + dd);
            float4 k1 = *(const float4*)(Ks + (tx + 16) * KPAD + dd);
            #pragma unroll
            for (int r = 0; r < 4; r++) {
                float4 q4 = *(const float4*)(Qs + (ty + 16 * r) * HD + dd);
                sc[r][0] += q4.x * k0.x + q4.y * k0.y + q4.z * k0.z + q4.w * k0.w;
                sc[r][1] += q4.x * k1.x + q4.y * k1.y + q4.z * k1.z + q4.w * k1.w;
            }
        }

        // ---- softcap, mask, online softmax ----
        float scale[4];
        #pragma unroll
        for (int r = 0; r < 4; r++) {
            const int ia = q0 + ty + 16 * r;
            float rmax = -1e30f;
            float pv[2];
            #pragma unroll
            for (int c = 0; c < 2; c++) {
                int ja = kb + tx + 16 * c;
                float s = sc[r][c] * 0.0625f;          // 256^-0.5
                s = 50.0f * tanhf(s * 0.02f);          // softcap
                bool ok = (ja <= ia) && (ia - ja < WINDOW);
                s = ok ? s : -1e9f;
                sc[r][c] = s;
                rmax = fmaxf(rmax, s);
            }
            #pragma unroll
            for (int off = 8; off; off >>= 1)
                rmax = fmaxf(rmax, __shfl_xor_sync(0xffffffffu, rmax, off));
            float nm = fmaxf(mrow[r], rmax);
            scale[r] = expf(mrow[r] - nm);
            mrow[r] = nm;
            float rsum = 0.f;
            #pragma unroll
            for (int c = 0; c < 2; c++) {
                float e = expf(sc[r][c] - nm);
                pv[c] = e; rsum += e;
            }
            #pragma unroll
            for (int off = 8; off; off >>= 1)
                rsum += __shfl_xor_sync(0xffffffffu, rsum, off);
            lrow[r] = lrow[r] * scale[r] + rsum;
            #pragma unroll
            for (int k = 0; k < 16; k++) o[r][k] *= scale[r];
            Ps[(ty + 16 * r) * ABN + tx]      = pv[0];
            Ps[(ty + 16 * r) * ABN + tx + 16] = pv[1];
        }
        __syncthreads();

        // ---- O += P V ----
        #pragma unroll 4
        for (int j = 0; j < ABN; j++) {
            float p0 = Ps[(ty     ) * ABN + j];
            float p1 = Ps[(ty + 16) * ABN + j];
            float p2 = Ps[(ty + 32) * ABN + j];
            float p3 = Ps[(ty + 48) * ABN + j];
            #pragma unroll
            for (int k = 0; k < 16; k++) {
                float v = Vs[j * KPAD + tx + 16 * k];
                o[0][k] += p0 * v;
                o[1][k] += p1 * v;
                o[2][k] += p2 * v;
                o[3][k] += p3 * v;
            }
        }
        __syncthreads();
    }

    // ---- epilogue ----
    #pragma unroll
    for (int r = 0; r < 4; r++) {
        float inv = 1.0f / lrow[r];
        size_t base = ((size_t)(q0 + ty + 16 * r) * NH + h) * HD;
        #pragma unroll
        for (int k = 0; k < 16; k++)
            O[base + tx + 16 * k] = o[r][k] * inv;
    }
}

// =====================================================================
// launch
// =====================================================================
extern "C" void kernel_launch(void* const* d_in, const int* in_sizes, int n_in,
                              void* d_out, int out_size)
{
    const float* hs   = (const float*)d_in[0];   // [1,2048,3584]
    const float* cosb = (const float*)d_in[1];   // [1,2048,256]
    const float* sinb = (const float*)d_in[2];   // [1,2048,256]
    const float* wq   = (const float*)d_in[3];   // [4096,3584]
    const float* wk   = (const float*)d_in[4];   // [2048,3584]
    const float* wv   = (const float*)d_in[5];   // [2048,3584]
    const float* wo   = (const float*)d_in[6];   // [3584,4096]
    float* out = (float*)d_out;                  // [1,2048,3584]

    float *pq, *pk, *pv, *pao;
    cudaGetSymbolAddress((void**)&pq,  g_q);
    cudaGetSymbolAddress((void**)&pk,  g_k);
    cudaGetSymbolAddress((void**)&pv,  g_v);
    cudaGetSymbolAddress((void**)&pao, g_ao);

    // QKV projections
    sgemm_tn<<<dim3(NH  * HD / 128, S_LEN / 128), 256>>>(hs, wq, pq, S_LEN, NH  * HD, HID);
    sgemm_tn<<<dim3(NKV * HD / 128, S_LEN / 128), 256>>>(hs, wk, pk, S_LEN, NKV * HD, HID);
    sgemm_tn<<<dim3(NKV * HD / 128, S_LEN / 128), 256>>>(hs, wv, pv, S_LEN, NKV * HD, HID);

    // RoPE (in place)
    {
        int tq = S_LEN * NH * 128;
        rope_kernel<<<(tq + 255) / 256, 256>>>(pq, cosb, sinb, NH);
        int tk = S_LEN * NKV * 128;
        rope_kernel<<<(tk + 255) / 256, 256>>>(pk, cosb, sinb, NKV);
    }

    // attention
    cudaFuncSetAttribute(attn_kernel, cudaFuncAttributeMaxDynamicSharedMemorySize,
                         (int)ATTN_SMEM);
    attn_kernel<<<dim3(S_LEN / ABM, NH), 256, ATTN_SMEM>>>(pq, pk, pv, pao);

    // output projection
    sgemm_tn<<<dim3(HID / 128, S_LEN / 128), 256>>>(pao, wo, out, S_LEN, HID, NH * HD);
}

// round 3
// speedup vs baseline: 1.0018x; 1.0018x over previous
#include <cuda_runtime.h>
#include <cuda_bf16.h>
#include <math.h>

// ---------------- problem constants ----------------
#define S_LEN   2048
#define HID     3584
#define NH      16
#define NKV     8
#define HD      256
#define GROUPS  2
#define WINDOW  1024

// scratch (device globals; no allocation allowed)
__device__ float g_q [S_LEN * NH  * HD];   // [s, h, d]   32 MB
__device__ float g_k [S_LEN * NKV * HD];   // [s, kh, d]  16 MB
__device__ float g_v [S_LEN * NKV * HD];   // [s, kh, d]  16 MB
__device__ float g_ao[S_LEN * NH  * HD];   // attention out, 32 MB

// =====================================================================
// SGEMM:  C[M,N] = A[M,K] * B[N,K]^T   (both row-major, K contiguous)
// 128x128 tile, BK=8, 256 threads, 8x8 per-thread microtile.
// M, N, K all divisible by 128 / 8 for every call in this problem.
// =====================================================================
__global__ __launch_bounds__(256) void sgemm_tn(
    const float* __restrict__ A, const float* __restrict__ B,
    float* __restrict__ C, int M, int N, int K)
{
    __shared__ float As[8][128];
    __shared__ float Bs[8][128];

    const int tid  = threadIdx.x;
    const int row0 = blockIdx.y * 128;
    const int col0 = blockIdx.x * 128;

    const int lrow = tid >> 1;         // 0..127
    const int lcol = (tid & 1) * 4;    // 0 or 4

    const float* Aptr = A + (size_t)(row0 + lrow) * K + lcol;
    const float* Bptr = B + (size_t)(col0 + lrow) * K + lcol;

    const int tr = tid >> 4;   // 0..15 -> rows tr*8..tr*8+7
    const int tc = tid & 15;   // 0..15 -> cols tc*8..tc*8+7

    float acc[8][8];
    #pragma unroll
    for (int i = 0; i < 8; i++)
        #pragma unroll
        for (int j = 0; j < 8; j++) acc[i][j] = 0.f;

    const int nk = K >> 3;
    float4 a4 = *(const float4*)Aptr;
    float4 b4 = *(const float4*)Bptr;

    for (int kt = 0; kt < nk; ++kt) {
        As[lcol + 0][lrow] = a4.x; As[lcol + 1][lrow] = a4.y;
        As[lcol + 2][lrow] = a4.z; As[lcol + 3][lrow] = a4.w;
        Bs[lcol + 0][lrow] = b4.x; Bs[lcol + 1][lrow] = b4.y;
        Bs[lcol + 2][lrow] = b4.z; Bs[lcol + 3][lrow] = b4.w;
        __syncthreads();

        if (kt + 1 < nk) {
            a4 = *(const float4*)(Aptr + (size_t)(kt + 1) * 8);
            b4 = *(const float4*)(Bptr + (size_t)(kt + 1) * 8);
        }

        #pragma unroll
        for (int k = 0; k < 8; ++k) {
            float ra[8], rb[8];
            *(float4*)&ra[0] = *(const float4*)&As[k][tr * 8];
            *(float4*)&ra[4] = *(const float4*)&As[k][tr * 8 + 4];
            *(float4*)&rb[0] = *(const float4*)&Bs[k][tc * 8];
            *(float4*)&rb[4] = *(const float4*)&Bs[k][tc * 8 + 4];
            #pragma unroll
            for (int i = 0; i < 8; i++)
                #pragma unroll
                for (int j = 0; j < 8; j++)
                    acc[i][j] += ra[i] * rb[j];
        }
        __syncthreads();
    }

    #pragma unroll
    for (int i = 0; i < 8; i++) {
        float* cp = C + (size_t)(row0 + tr * 8 + i) * N + col0 + tc * 8;
        float4 c0 = make_float4(acc[i][0], acc[i][1], acc[i][2], acc[i][3]);
        float4 c1 = make_float4(acc[i][4], acc[i][5], acc[i][6], acc[i][7]);
        *(float4*)cp       = c0;
        *(float4*)(cp + 4) = c1;
    }
}

// =====================================================================
// RoPE in-place: x layout [s, nheads, 256].
// cos/sin: [s, 256] with cos[s][d] == cos[s][d+128] by construction.
// =====================================================================
__global__ void rope_kernel(float* __restrict__ x,
                            const float* __restrict__ cosb,
                            const float* __restrict__ sinb,
                            int nheads)
{
    int idx = blockIdx.x * blockDim.x + threadIdx.x;
    int total = S_LEN * nheads * 128;
    if (idx >= total) return;
    int d = idx & 127;
    int t = idx >> 7;
    int h = t % nheads;
    int s = t / nheads;
    float c  = cosb[s * HD + d];
    float sn = sinb[s * HD + d];
    float* p = x + ((size_t)s * nheads + h) * HD;
    float x1 = p[d], x2 = p[d + 128];
    p[d]       = x1 * c - x2 * sn;
    p[d + 128] = x2 * c + x1 * sn;
}

// =====================================================================
// Flash-style sliding-window attention with softcap.
// grid = (S/64, NH), 256 threads.
// Each block: 64 queries of one head. Key tiles of 32, online softmax.
// Thread layout: ty = tid/16 (0..15), tx = tid%16.
//   rows owned:   i = ty + 16r,  r in 0..3
//   score cols:   j = tx + 16c,  c in 0..1
//   O cols owned: d = tx + 16k,  k in 0..15
// =====================================================================
#define ABM   64
#define ABN   32
#define KPAD  260   // 260*4 bytes per row, 16B-aligned, conflict-free
#define ATTN_SMEM ((ABM*HD + 2*ABN*KPAD + ABM*ABN) * sizeof(float))

__global__ __launch_bounds__(256) void attn_kernel(
    const float* __restrict__ Q, const float* __restrict__ Kb,
    const float* __restrict__ Vb, float* __restrict__ O)
{
    extern __shared__ float sm[];
    float* Qs = sm;                      // [64][256]
    float* Ks = Qs + ABM * HD;           // [32][260]
    float* Vs = Ks + ABN * KPAD;         // [32][260]
    float* Ps = Vs + ABN * KPAD;         // [64][32]

    const int tid = threadIdx.x;
    const int tx = tid & 15, ty = tid >> 4;
    const int q0 = blockIdx.x * ABM;
    const int h  = blockIdx.y;
    const int kvh = h / GROUPS;

    // ---- load Q tile ----
    #pragma unroll
    for (int t = 0; t < 16; ++t) {
        int f4  = tid + 256 * t;            // 4096 float4 total
        int row = f4 >> 6;                  // 64 float4 per row
        int c4  = (f4 & 63) << 2;
        float4 v = *(const float4*)(Q + ((size_t)(q0 + row) * NH + h) * HD + c4);
        *(float4*)(Qs + row * HD + c4) = v;
    }

    float o[4][16];
    float mrow[4], lrow[4];
    #pragma unroll
    for (int r = 0; r < 4; r++) {
        mrow[r] = -1e30f; lrow[r] = 0.f;
        #pragma unroll
        for (int k = 0; k < 16; k++) o[r][k] = 0.f;
    }

    int jlo = q0 - (WINDOW - 1); if (jlo < 0) jlo = 0;
    const int t0   = (jlo >> 5) << 5;
    const int tend = q0 + ABM;

    __syncthreads();  // Qs visible

    for (int kb = t0; kb < tend; kb += ABN) {
        // ---- load K,V tile ----
        #pragma unroll
        for (int t = 0; t < 8; ++t) {
            int f4  = tid + 256 * t;        // 2048 float4
            int row = f4 >> 6;
            int c4  = (f4 & 63) << 2;
            size_t gb = ((size_t)(kb + row) * NKV + kvh) * HD + c4;
            *(float4*)(Ks + row * KPAD + c4) = *(const float4*)(Kb + gb);
            *(float4*)(Vs + row * KPAD + c4) = *(const float4*)(Vb + gb);
        }
        __syncthreads();

        // ---- scores: S = Q K^T ----
        float sc[4][2];
        #pragma unroll
        for (int r = 0; r < 4; r++) { sc[r][0] = 0.f; sc[r][1] = 0.f; }

        #pragma unroll 4
        for (int dd = 0; dd < HD; dd += 4) {
            float4 k0 = *(const float4*)(Ks + tx * KPAD + dd);
            float4 k1 = *(const float4*)(Ks + (tx + 16) * KPAD + dd);
            #pragma unroll
            for (int r = 0; r < 4; r++) {
                float4 q4 = *(const float4*)(Qs + (ty + 16 * r) * HD + dd);
                sc[r][0] += q4.x * k0.x + q4.y * k0.y + q4.z * k0.z + q4.w * k0.w;
                sc[r][1] += q4.x * k1.x + q4.y * k1.y + q4.z * k1.z + q4.w * k1.w;
            }
        }

        // ---- softcap, mask, online softmax ----
        float scale[4];
        #pragma unroll
        for (int r = 0; r < 4; r++) {
            const int ia = q0 + ty + 16 * r;
            float rmax = -1e30f;
            float pv[2];
            #pragma unroll
            for (int c = 0; c < 2; c++) {
                int ja = kb + tx + 16 * c;
                float s = sc[r][c] * 0.0625f;          // 256^-0.5
                s = 50.0f * tanhf(s * 0.02f);          // softcap
                bool ok = (ja <= ia) && (ia - ja < WINDOW);
                s = ok ? s : -1e9f;
                sc[r][c] = s;
                rmax = fmaxf(rmax, s);
            }
            #pragma unroll
            for (int off = 8; off; off >>= 1)
                rmax = fmaxf(rmax, __shfl_xor_sync(0xffffffffu, rmax, off));
            float nm = fmaxf(mrow[r], rmax);
            scale[r] = expf(mrow[r] - nm);
            mrow[r] = nm;
            float rsum = 0.f;
            #pragma unroll
            for (int c = 0; c < 2; c++) {
                float e = expf(sc[r][c] - nm);
                pv[c] = e; rsum += e;
            }
            #pragma unroll
            for (int off = 8; off; off >>= 1)
                rsum += __shfl_xor_sync(0xffffffffu, rsum, off);
            lrow[r] = lrow[r] * scale[r] + rsum;
            #pragma unroll
            for (int k = 0; k < 16; k++) o[r][k] *= scale[r];
            Ps[(ty + 16 * r) * ABN + tx]      = pv[0];
            Ps[(ty + 16 * r) * ABN + tx + 16] = pv[1];
        }
        __syncthreads();

        // ---- O += P V ----
        #pragma unroll 4
        for (int j = 0; j < ABN; j++) {
            float p0 = Ps[(ty     ) * ABN + j];
            float p1 = Ps[(ty + 16) * ABN + j];
            float p2 = Ps[(ty + 32) * ABN + j];
            float p3 = Ps[(ty + 48) * ABN + j];
            #pragma unroll
            for (int k = 0; k < 16; k++) {
                float v = Vs[j * KPAD + tx + 16 * k];
                o[0][k] += p0 * v;
                o[1][k] += p1 * v;
                o[2][k] += p2 * v;
                o[3][k] += p3 * v;
            }
        }
        __syncthreads();
    }

    // ---- epilogue ----
    #pragma unroll
    for (int r = 0; r < 4; r++) {
        float inv = 1.0f / lrow[r];
        size_t base = ((size_t)(q0 + ty + 16 * r) * NH + h) * HD;
        #pragma unroll
        for (int k = 0; k < 16; k++)
            O[base + tx + 16 * k] = o[r][k] * inv;
    }
}

// =====================================================================
// launch
// =====================================================================
extern "C" void kernel_launch(void* const* d_in, const int* in_sizes, int n_in,
                              void* d_out, int out_size)
{
    const float* hs   = (const float*)d_in[0];   // [1,2048,3584]
    const float* cosb = (const float*)d_in[1];   // [1,2048,256]
    const float* sinb = (const float*)d_in[2];   // [1,2048,256]
    const float* wq   = (const float*)d_in[3];   // [4096,3584]
    const float* wk   = (const float*)d_in[4];   // [2048,3584]
    const float* wv   = (const float*)d_in[5];   // [2048,3584]
    const float* wo   = (const float*)d_in[6];   // [3584,4096]
    float* out = (float*)d_out;                  // [1,2048,3584]

    float *pq, *pk, *pv, *pao;
    cudaGetSymbolAddress((void**)&pq,  g_q);
    cudaGetSymbolAddress((void**)&pk,  g_k);
    cudaGetSymbolAddress((void**)&pv,  g_v);
    cudaGetSymbolAddress((void**)&pao, g_ao);

    // QKV projections
    sgemm_tn<<<dim3(NH  * HD / 128, S_LEN / 128), 256>>>(hs, wq, pq, S_LEN, NH  * HD, HID);
    sgemm_tn<<<dim3(NKV * HD / 128, S_LEN / 128), 256>>>(hs, wk, pk, S_LEN, NKV * HD, HID);
    sgemm_tn<<<dim3(NKV * HD / 128, S_LEN / 128), 256>>>(hs, wv, pv, S_LEN, NKV * HD, HID);

    // RoPE (in place)
    {
        int tq = S_LEN * NH * 128;
        rope_kernel<<<(tq + 255) / 256, 256>>>(pq, cosb, sinb, NH);
        int tk = S_LEN * NKV * 128;
        rope_kernel<<<(tk + 255) / 256, 256>>>(pk, cosb, sinb, NKV);
    }

    // attention
    cudaFuncSetAttribute(attn_kernel, cudaFuncAttributeMaxDynamicSharedMemorySize,
                         (int)ATTN_SMEM);
    attn_kernel<<<dim3(S_LEN / ABM, NH), 256, ATTN_SMEM>>>(pq, pk, pv, pao);

    // output projection
    sgemm_tn<<<dim3(HID / 128, S_LEN / 128), 256>>>(pao, wo, out, S_LEN, HID, NH * HD);
}